// round 2
// baseline (speedup 1.0000x reference)
#include <cuda_runtime.h>

#define N_USER_MAX 27094
#define M_SPOT_MAX 42852

// Degree scratch (allocation-free per harness rules)
__device__ int g_user_deg[N_USER_MAX];
__device__ int g_spot_deg[M_SPOT_MAX];

__global__ void zero_deg_kernel(int n_user, int m_spot) {
    int i = blockIdx.x * blockDim.x + threadIdx.x;
    if (i < n_user) g_user_deg[i] = 0;
    if (i < m_spot) g_spot_deg[i] = 0;
}

__global__ void deg_kernel(const int* __restrict__ es, int E) {
    int e = blockIdx.x * blockDim.x + threadIdx.x;
    if (e < E) {
        atomicAdd(&g_user_deg[__ldg(es + e)], 1);      // u = es[0, e]
        atomicAdd(&g_spot_deg[__ldg(es + E + e)], 1);  // s = es[1, e]
    }
}

// Vectorized no-return global reduction: one 16B op instead of 4 scalar REDGs.
__device__ __forceinline__ void red_add_v4(float* ptr, float4 v) {
    asm volatile("red.global.add.v4.f32 [%0], {%1, %2, %3, %4};"
                 :: "l"(ptr), "f"(v.x), "f"(v.y), "f"(v.z), "f"(v.w)
                 : "memory");
}

// One warp per edge. Lane l handles feature floats [4l, 4l+4).
__global__ void __launch_bounds__(256, 8)
scatter_kernel(const float4* __restrict__ spot_x,
               const float4* __restrict__ user_x,
               const int* __restrict__ es, int E,
               float4* __restrict__ spot_out,
               float4* __restrict__ user_out) {
    long long gtid = (long long)blockIdx.x * blockDim.x + threadIdx.x;
    int warp = (int)(gtid >> 5);
    int lane = threadIdx.x & 31;
    if (warp >= E) return;

    // Warp-uniform broadcast loads
    int u = __ldg(es + warp);
    int s = __ldg(es + E + warp);
    float du = (float)__ldg(&g_user_deg[u]);
    float ds = (float)__ldg(&g_spot_deg[s]);
    float scale = rsqrtf(du * ds);

    // Coalesced 512B row gathers (L2-resident after first wave)
    float4 sv = __ldg(spot_x + (size_t)s * 32 + lane);
    float4 uv = __ldg(user_x + (size_t)u * 32 + lane);

    sv.x *= scale; sv.y *= scale; sv.z *= scale; sv.w *= scale;
    uv.x *= scale; uv.y *= scale; uv.z *= scale; uv.w *= scale;

    red_add_v4((float*)(user_out + (size_t)u * 32 + lane), sv);
    red_add_v4((float*)(spot_out + (size_t)s * 32 + lane), uv);
}

extern "C" void kernel_launch(void* const* d_in, const int* in_sizes, int n_in,
                              void* d_out, int out_size) {
    const float* spot_x = (const float*)d_in[0];   // [M_SPOT, 128]
    const float* user_x = (const float*)d_in[1];   // [N_USER, 128]
    const int*   es     = (const int*)d_in[2];     // [2, E]

    int m_spot = in_sizes[0] / 128;
    int n_user = in_sizes[1] / 128;
    int E      = in_sizes[2] / 2;

    float* out      = (float*)d_out;
    float* spot_out = out;                          // [M_SPOT, 128] first
    float* user_out = out + (size_t)m_spot * 128;   // then [N_USER, 128]

    // Zero output (poisoned to 0xAA by harness) and degree scratch
    cudaMemsetAsync(d_out, 0, (size_t)out_size * sizeof(float));
    {
        int n = (m_spot > n_user) ? m_spot : n_user;
        zero_deg_kernel<<<(n + 255) / 256, 256>>>(n_user, m_spot);
    }

    // Degrees
    deg_kernel<<<(E + 255) / 256, 256>>>(es, E);

    // Main scatter: one warp per edge, 8 warps per block
    int blocks = (E + 7) / 8;
    scatter_kernel<<<blocks, 256>>>((const float4*)spot_x, (const float4*)user_x,
                                    es, E, (float4*)spot_out, (float4*)user_out);
}

// round 12
// speedup vs baseline: 1.6483x; 1.6483x over previous
#include <cuda_runtime.h>

#define N_USERC 27094
#define M_SPOTC 42852
#define E_MAXC  2000000

// ── CSR scratch (allocation-free: __device__ globals) ──
__device__ int   g_udeg[N_USERC];
__device__ int   g_sdeg[M_SPOTC];
__device__ float g_urs[N_USERC];       // rsqrt(deg)
__device__ float g_srs[M_SPOTC];
__device__ int   g_uoff[N_USERC + 1];
__device__ int   g_soff[M_SPOTC + 1];
__device__ int   g_ucur[N_USERC];
__device__ int   g_scur[M_SPOTC];
__device__ int2  g_uadj[E_MAXC];       // {spot idx, edge weight} grouped by user
__device__ int2  g_sadj[E_MAXC];       // {user idx, edge weight} grouped by spot

__global__ void zero_kernel() {
    int i = blockIdx.x * blockDim.x + threadIdx.x;
    if (i < N_USERC) g_udeg[i] = 0;
    if (i < M_SPOTC) g_sdeg[i] = 0;
}

__global__ void deg_kernel(const int* __restrict__ es, int E) {
    int e = blockIdx.x * blockDim.x + threadIdx.x;
    if (e < E) {
        atomicAdd(&g_udeg[__ldg(es + e)], 1);
        atomicAdd(&g_sdeg[__ldg(es + E + e)], 1);
    }
}

__global__ void rsqrt_kernel() {
    int i = blockIdx.x * blockDim.x + threadIdx.x;
    if (i < N_USERC) g_urs[i] = g_udeg[i] ? rsqrtf((float)g_udeg[i]) : 0.f;
    if (i < M_SPOTC) g_srs[i] = g_sdeg[i] ? rsqrtf((float)g_sdeg[i]) : 0.f;
}

// grid=2: block 0 scans user degrees, block 1 spot degrees. 1024 threads.
__global__ void scan_kernel() {
    const int* deg; int* off; int* cur; int n;
    if (blockIdx.x == 0) { deg = g_udeg; off = g_uoff; cur = g_ucur; n = N_USERC; }
    else                 { deg = g_sdeg; off = g_soff; cur = g_scur; n = M_SPOTC; }

    __shared__ int wsum[32];
    __shared__ int carry_s;
    int tid = threadIdx.x, lane = tid & 31, wid = tid >> 5;
    if (tid == 0) carry_s = 0;
    __syncthreads();

    for (int base = 0; base < n; base += 1024) {
        int i = base + tid;
        int v = (i < n) ? deg[i] : 0;
        int x = v;
        #pragma unroll
        for (int d = 1; d < 32; d <<= 1) {
            int y = __shfl_up_sync(0xffffffffu, x, d);
            if (lane >= d) x += y;
        }
        if (lane == 31) wsum[wid] = x;
        __syncthreads();
        if (wid == 0) {
            int w = wsum[lane], xx = w;
            #pragma unroll
            for (int d = 1; d < 32; d <<= 1) {
                int y = __shfl_up_sync(0xffffffffu, xx, d);
                if (lane >= d) xx += y;
            }
            wsum[lane] = xx - w;  // exclusive warp offset
        }
        __syncthreads();
        int excl = x - v + wsum[wid] + carry_s;
        if (i < n) { off[i] = excl; cur[i] = excl; }
        __syncthreads();
        if (tid == 1023) carry_s = excl + v;
        __syncthreads();
    }
    if (tid == 0) off[n] = carry_s;
}

// Pack per-edge weight w = urs[u]*srs[s] into the adjacency entries so the
// bandwidth-critical gather never does random scalar lookups.
__global__ void fill_kernel(const int* __restrict__ es, int E) {
    int e = blockIdx.x * blockDim.x + threadIdx.x;
    if (e < E) {
        int u = __ldg(es + e), s = __ldg(es + E + e);
        float w = __ldg(&g_urs[u]) * __ldg(&g_srs[s]);
        int wi = __float_as_int(w);
        g_uadj[atomicAdd(&g_ucur[u], 1)] = make_int2(s, wi);
        g_sadj[atomicAdd(&g_scur[s], 1)] = make_int2(u, wi);
    }
}

// Fused gather: warps [0, N_USERC) do user <- spot, warps [N_USERC, ...) do
// spot <- user. One warp per destination node; lane l owns floats [4l, 4l+4).
// Adjacency (idx, weight) batch-loaded coalesced, broadcast via shfl.
__global__ void __launch_bounds__(256, 8)
gather_kernel(const float4* __restrict__ spot_x,
              const float4* __restrict__ user_x,
              float4* __restrict__ user_out,
              float4* __restrict__ spot_out) {
    int gw = (int)(((long long)blockIdx.x * blockDim.x + threadIdx.x) >> 5);
    int lane = threadIdx.x & 31;

    const int* off; const int2* adj; const float4* src; float4* out;
    int node;

    if (gw < N_USERC) {
        node = gw;
        off = g_uoff; adj = g_uadj; src = spot_x; out = user_out;
    } else if (gw < N_USERC + M_SPOTC) {
        node = gw - N_USERC;
        off = g_soff; adj = g_sadj; src = user_x; out = spot_out;
    } else {
        return;
    }

    int beg = __ldg(&off[node]);
    int end = __ldg(&off[node + 1]);
    float4 acc = make_float4(0.f, 0.f, 0.f, 0.f);

    for (int base = beg; base < end; base += 32) {
        int j = base + lane;
        int2 aw = make_int2(0, 0);
        if (j < end) aw = __ldg(&adj[j]);          // coalesced 8B loads
        int m = end - base; if (m > 32) m = 32;
        if (m == 32) {
            #pragma unroll 8
            for (int t = 0; t < 32; t++) {
                int   s2 = __shfl_sync(0xffffffffu, aw.x, t);
                float ww = __int_as_float(__shfl_sync(0xffffffffu, aw.y, t));
                float4 v = __ldg(src + (size_t)s2 * 32 + lane);
                acc.x += v.x * ww; acc.y += v.y * ww;
                acc.z += v.z * ww; acc.w += v.w * ww;
            }
        } else {
            for (int t = 0; t < m; t++) {
                int   s2 = __shfl_sync(0xffffffffu, aw.x, t);
                float ww = __int_as_float(__shfl_sync(0xffffffffu, aw.y, t));
                float4 v = __ldg(src + (size_t)s2 * 32 + lane);
                acc.x += v.x * ww; acc.y += v.y * ww;
                acc.z += v.z * ww; acc.w += v.w * ww;
            }
        }
    }

    // Streaming store: bypass L1 (keep it for gathers), write-through L2.
    __stcg(&out[(size_t)node * 32 + lane], acc);
}

extern "C" void kernel_launch(void* const* d_in, const int* in_sizes, int n_in,
                              void* d_out, int out_size) {
    const float* spot_x = (const float*)d_in[0];   // [M_SPOT, 128]
    const float* user_x = (const float*)d_in[1];   // [N_USER, 128]
    const int*   es     = (const int*)d_in[2];     // [2, E]

    int m_spot = in_sizes[0] / 128;
    int E      = in_sizes[2] / 2;

    float* out      = (float*)d_out;
    float* spot_out = out;                          // [M_SPOT, 128] first
    float* user_out = out + (size_t)m_spot * 128;   // then [N_USER, 128]

    // CSR build
    zero_kernel <<<(M_SPOTC + 255) / 256, 256>>>();
    deg_kernel  <<<(E + 255) / 256, 256>>>(es, E);
    rsqrt_kernel<<<(M_SPOTC + 255) / 256, 256>>>();
    scan_kernel <<<2, 1024>>>();
    fill_kernel <<<(E + 255) / 256, 256>>>(es, E);

    // Fused gather over both node sets — writes every output element, no memset.
    int total_warps = N_USERC + M_SPOTC;
    gather_kernel<<<(total_warps * 32 + 255) / 256, 256>>>(
        (const float4*)spot_x, (const float4*)user_x,
        (float4*)user_out, (float4*)spot_out);
}